// round 16
// baseline (speedup 1.0000x reference)
#include <cuda_runtime.h>
#include <cuda_fp16.h>

#define CH 64
#define MAXN 65536
#define MAXDEG 64

// Scratch (no allocs allowed).
__device__ int     g_deg[MAXN];
__device__ int     g_bucket[(size_t)MAXN * MAXDEG];
__device__ __half2 g_xh[(size_t)MAXN * 32];      // x in fp16, half2-packed pairs
__device__ float   g_colsum[CH];
__device__ float   g_sumsq[CH];
__device__ int     g_idx64;

// ---- dynamic smem layout for k_mlp (bytes) ----
#define PW 68                      // padded row pitch (floats): bank = 4g+t, conflict-free
#define SZW (64 * PW * 4)          // 17408 per weight array
#define SM_W0HI 0
#define SM_W0LO (SZW)
#define SM_W1HI (2 * SZW)
#define SM_W1LO (3 * SZW)
#define SM_H    (4 * SZW)                      // 8 warps x 16 rows x PW floats
#define SM_LNP  (SM_H + 8 * 16 * PW * 4)       // ln0w|ln0b|ln1w|ln1b (4 x 64 f32)
#define SM_BSUM (SM_LNP + 1024)                // bsum[64], bss[64]
#define SM_TOTAL (SM_BSUM + 512)

// ---------------------------------------------------------------------------
// K1: zero deg + reduction buffers, detect index dtype, convert x -> fp16.
// ---------------------------------------------------------------------------
__global__ void k_prep(const float2* __restrict__ x2, const int* __restrict__ ei32,
                       int N, int E) {
    int i = blockIdx.x * blockDim.x + threadIdx.x;
    if (i < N) g_deg[i] = 0;
    const int total = N * 32;
    for (int j = i; j < total; j += gridDim.x * blockDim.x)
        g_xh[j] = __float22half2_rn(x2[j]);
    if (blockIdx.x == 0) {
        if (threadIdx.x < CH) { g_colsum[threadIdx.x] = 0.f; g_sumsq[threadIdx.x] = 0.f; }
        if (threadIdx.x == 0) {
            // int64 edge_index => high 32-bit word of every entry is 0.
            int allz = 1;
            int cnt = (E < 64) ? E : 64;
            for (int t = 0; t < cnt; t++) allz &= (ei32[2 * t + 1] == 0);
            g_idx64 = allz;
        }
    }
}

// ---------------------------------------------------------------------------
// K2: single-pass bucket scatter; slot = atomic return value.
// ---------------------------------------------------------------------------
__global__ void k_bucket(const void* __restrict__ ei, int E) {
    const int idx64 = g_idx64;
    const long long* e64 = (const long long*)ei;
    const int*       e32 = (const int*)ei;
    int i = blockIdx.x * blockDim.x + threadIdx.x;
    if (i < E) {
        int src, dst;
        if (idx64) { src = (int)e64[i]; dst = (int)e64[E + i]; }
        else       { src = e32[i];      dst = e32[E + i]; }
        int slot = atomicAdd(&g_deg[dst], 1);
        if (slot < MAXDEG)
            g_bucket[(size_t)dst * MAXDEG + slot] = src;
    }
}

// ---------------------------------------------------------------------------
// K3: dedicated gather — warp per row. Neighbors read as fp16 (128B/row:
// halves the L2 stream vs fp32), self row in fp32, accumulation in fp32.
// agg written into `out` (k_mlp reads it back before overwriting).
// ---------------------------------------------------------------------------
__global__ void __launch_bounds__(256)
k_gather(const float* __restrict__ x, float* __restrict__ agg, int N) {
    const int lane = threadIdx.x & 31;
    const int row  = blockIdx.x * 8 + (threadIdx.x >> 5);
    if (row >= N) return;
    const float2* x2 = reinterpret_cast<const float2*>(x);
    int deg = g_deg[row];
    if (deg > MAXDEG) deg = MAXDEG;
    const int* nb = g_bucket + (size_t)row * MAXDEG;
    float2 acc0 = x2[row * 32 + lane];
    float2 acc1 = make_float2(0.f, 0.f);
    float2 acc2 = make_float2(0.f, 0.f);
    float2 acc3 = make_float2(0.f, 0.f);
    int j = 0;
    for (; j + 4 <= deg; j += 4) {
        int s0 = nb[j];
        int s1 = nb[j + 1];
        int s2 = nb[j + 2];
        int s3 = nb[j + 3];
        float2 v0 = __half22float2(g_xh[s0 * 32 + lane]);
        float2 v1 = __half22float2(g_xh[s1 * 32 + lane]);
        float2 v2 = __half22float2(g_xh[s2 * 32 + lane]);
        float2 v3 = __half22float2(g_xh[s3 * 32 + lane]);
        acc0.x += v0.x; acc0.y += v0.y;
        acc1.x += v1.x; acc1.y += v1.y;
        acc2.x += v2.x; acc2.y += v2.y;
        acc3.x += v3.x; acc3.y += v3.y;
    }
    for (; j < deg; j++) {
        int s0 = nb[j];
        float2 v0 = __half22float2(g_xh[s0 * 32 + lane]);
        acc0.x += v0.x; acc0.y += v0.y;
    }
    acc0.x += acc1.x; acc0.y += acc1.y;
    acc2.x += acc3.x; acc2.y += acc3.y;
    acc0.x += acc2.x; acc0.y += acc2.y;
    reinterpret_cast<float2*>(agg)[row * 32 + lane] = acc0;
}

// ---------------------------------------------------------------------------
// tf32 helpers
// ---------------------------------------------------------------------------
__device__ __forceinline__ unsigned f2tf(float x) {
    unsigned r;
    asm("cvt.rna.tf32.f32 %0, %1;" : "=r"(r) : "f"(x));
    return r;
}
__device__ __forceinline__ void tf32_split(float x, unsigned& hi, unsigned& lo) {
    asm("cvt.rna.tf32.f32 %0, %1;" : "=r"(hi) : "f"(x));
    float r = x - __uint_as_float(hi);
    asm("cvt.rna.tf32.f32 %0, %1;" : "=r"(lo) : "f"(r));
}
__device__ __forceinline__ void mma8(float d[4], unsigned a0, unsigned a1,
                                     unsigned a2, unsigned a3,
                                     unsigned b0, unsigned b1) {
    asm("mma.sync.aligned.m16n8k8.row.col.f32.tf32.tf32.f32 "
        "{%0,%1,%2,%3}, {%4,%5,%6,%7}, {%8,%9}, {%0,%1,%2,%3};"
        : "+f"(d[0]), "+f"(d[1]), "+f"(d[2]), "+f"(d[3])
        : "r"(a0), "r"(a1), "r"(a2), "r"(a3), "r"(b0), "r"(b1));
}

// One 16x64x64 layer with 3xTF32: D = h @ W^T. hw: [16][PW] row-major smem.
// whi/wlo: [64][PW] smem (pre-split). Lane = (g = lane>>2, t = lane&3).
__device__ __forceinline__ void mma_layer(
    const float* __restrict__ hw, const float* __restrict__ whi,
    const float* __restrict__ wlo, int g, int t, float D[8][4]) {
    #pragma unroll
    for (int n = 0; n < 8; n++) { D[n][0] = D[n][1] = D[n][2] = D[n][3] = 0.f; }
    #pragma unroll
    for (int ks = 0; ks < 8; ks++) {
        const int k0 = ks * 8 + t;
        unsigned ah0, al0, ah1, al1, ah2, al2, ah3, al3;
        tf32_split(hw[g * PW + k0],           ah0, al0);
        tf32_split(hw[(g + 8) * PW + k0],     ah1, al1);
        tf32_split(hw[g * PW + k0 + 4],       ah2, al2);
        tf32_split(hw[(g + 8) * PW + k0 + 4], ah3, al3);
        #pragma unroll
        for (int n = 0; n < 8; n++) {
            const int col = 8 * n + g;
            unsigned bh0 = __float_as_uint(whi[col * PW + k0]);
            unsigned bh1 = __float_as_uint(whi[col * PW + k0 + 4]);
            unsigned bl0 = __float_as_uint(wlo[col * PW + k0]);
            unsigned bl1 = __float_as_uint(wlo[col * PW + k0 + 4]);
            mma8(D[n], ah0, ah1, ah2, ah3, bh0, bh1);
            mma8(D[n], ah0, ah1, ah2, ah3, bl0, bl1);
            mma8(D[n], al0, al1, al2, al3, bh0, bh1);
        }
    }
}

// LayerNorm + ReLU on mma-layout D, writing normalized rows into hw smem.
// Row g in D[n][0..1], row g+8 in D[n][2..3]; cols = 8n + 2t (+1).
__device__ __forceinline__ void ln_stage(
    float D[8][4], const float* __restrict__ lw, const float* __restrict__ lb,
    int g, int t, float* __restrict__ hw) {
    float s0 = 0.f, s1 = 0.f;
    #pragma unroll
    for (int n = 0; n < 8; n++) { s0 += D[n][0] + D[n][1]; s1 += D[n][2] + D[n][3]; }
    s0 += __shfl_xor_sync(0xffffffffu, s0, 1);
    s0 += __shfl_xor_sync(0xffffffffu, s0, 2);
    s1 += __shfl_xor_sync(0xffffffffu, s1, 1);
    s1 += __shfl_xor_sync(0xffffffffu, s1, 2);
    float mu0 = s0 * (1.f / 64.f), mu1 = s1 * (1.f / 64.f);
    float q0 = 0.f, q1 = 0.f;
    #pragma unroll
    for (int n = 0; n < 8; n++) {
        float d0 = D[n][0] - mu0, d1 = D[n][1] - mu0;
        float d2 = D[n][2] - mu1, d3 = D[n][3] - mu1;
        q0 += d0 * d0 + d1 * d1;
        q1 += d2 * d2 + d3 * d3;
    }
    q0 += __shfl_xor_sync(0xffffffffu, q0, 1);
    q0 += __shfl_xor_sync(0xffffffffu, q0, 2);
    q1 += __shfl_xor_sync(0xffffffffu, q1, 1);
    q1 += __shfl_xor_sync(0xffffffffu, q1, 2);
    float inv0 = rsqrtf(q0 * (1.f / 64.f) + 1e-5f);
    float inv1 = rsqrtf(q1 * (1.f / 64.f) + 1e-5f);
    #pragma unroll
    for (int n = 0; n < 8; n++) {
        int c = 8 * n + 2 * t;
        float2 w2 = *reinterpret_cast<const float2*>(&lw[c]);
        float2 b2 = *reinterpret_cast<const float2*>(&lb[c]);
        float2 r0, r1;
        r0.x = fmaxf(fmaf((D[n][0] - mu0) * inv0, w2.x, b2.x), 0.f);
        r0.y = fmaxf(fmaf((D[n][1] - mu0) * inv0, w2.y, b2.y), 0.f);
        r1.x = fmaxf(fmaf((D[n][2] - mu1) * inv1, w2.x, b2.x), 0.f);
        r1.y = fmaxf(fmaf((D[n][3] - mu1) * inv1, w2.y, b2.y), 0.f);
        *reinterpret_cast<float2*>(&hw[g * PW + c])       = r0;
        *reinterpret_cast<float2*>(&hw[(g + 8) * PW + c]) = r1;
    }
}

// ---------------------------------------------------------------------------
// K4: MLP via tensor cores (mma.sync tf32, 3xTF32). Warp = 16 rows.
// 8 warps/block share one pre-split weight copy. Dynamic smem ~104KB,
// 2 CTAs/SM. GraphNorm partials fused in epilogue.
// ---------------------------------------------------------------------------
__global__ void __launch_bounds__(256, 2)
k_mlp(const float* __restrict__ W0, const float* __restrict__ ln0w,
      const float* __restrict__ ln0b, const float* __restrict__ W1,
      const float* __restrict__ ln1w, const float* __restrict__ ln1b,
      float* __restrict__ out, int N) {
    extern __shared__ __align__(16) char dsm[];
    float* w0hi = reinterpret_cast<float*>(dsm + SM_W0HI);
    float* w0lo = reinterpret_cast<float*>(dsm + SM_W0LO);
    float* w1hi = reinterpret_cast<float*>(dsm + SM_W1HI);
    float* w1lo = reinterpret_cast<float*>(dsm + SM_W1LO);
    float* lnp  = reinterpret_cast<float*>(dsm + SM_LNP);
    float* bsum = reinterpret_cast<float*>(dsm + SM_BSUM);
    float* bss  = bsum + CH;

    const int tid  = threadIdx.x;
    const int lane = tid & 31;
    const int warp = tid >> 5;
    const int g    = lane >> 2;
    const int t    = lane & 3;

    float* hw = reinterpret_cast<float*>(dsm + SM_H) + warp * 16 * PW;

    // ---- pre-split weights into tf32 hi/lo (once per block) ----
    for (int i = tid; i < CH * CH; i += blockDim.x) {
        int r = i >> 6, c = i & 63;
        float w = W0[i];
        unsigned hb = f2tf(w);
        float hf = __uint_as_float(hb);
        w0hi[r * PW + c] = hf;
        w0lo[r * PW + c] = __uint_as_float(f2tf(w - hf));
        float v = W1[i];
        unsigned hb1 = f2tf(v);
        float hf1 = __uint_as_float(hb1);
        w1hi[r * PW + c] = hf1;
        w1lo[r * PW + c] = __uint_as_float(f2tf(v - hf1));
    }
    if (tid < CH) {
        lnp[tid]       = ln0w[tid];
        lnp[64 + tid]  = ln0b[tid];
        lnp[128 + tid] = ln1w[tid];
        lnp[192 + tid] = ln1b[tid];
        bsum[tid] = 0.f;
        bss[tid]  = 0.f;
    }
    __syncthreads();

    const int base = (blockIdx.x * 8 + warp) * 16;
    const float2* o2 = reinterpret_cast<const float2*>(out);

    // ---- stage 16 agg rows (coalesced) into row-major smem ----
    #pragma unroll
    for (int r = 0; r < 16; r++) {
        int row = base + r;
        float2 v = (row < N) ? o2[row * 32 + lane] : make_float2(0.f, 0.f);
        *reinterpret_cast<float2*>(&hw[r * PW + 2 * lane]) = v;
    }
    __syncwarp();

    float D[8][4];

    // ---- layer 0: GEMM (tensor) -> LN -> ReLU back into hw ----
    mma_layer(hw, w0hi, w0lo, g, t, D);
    __syncwarp();
    ln_stage(D, lnp, lnp + 64, g, t, hw);
    __syncwarp();

    // ---- layer 1 ----
    mma_layer(hw, w1hi, w1lo, g, t, D);
    __syncwarp();
    ln_stage(D, lnp + 128, lnp + 192, g, t, hw);
    __syncwarp();

    // ---- epilogue: coalesced store + GraphNorm partials ----
    float cs0 = 0.f, cs1 = 0.f, ss0 = 0.f, ss1 = 0.f;
    #pragma unroll
    for (int r = 0; r < 16; r++) {
        int row = base + r;
        if (row < N) {
            float2 v = *reinterpret_cast<const float2*>(&hw[r * PW + 2 * lane]);
            reinterpret_cast<float2*>(out)[row * 32 + lane] = v;
            cs0 += v.x; cs1 += v.y;
            ss0 = fmaf(v.x, v.x, ss0);
            ss1 = fmaf(v.y, v.y, ss1);
        }
    }
    atomicAdd(&bsum[2 * lane], cs0);
    atomicAdd(&bsum[2 * lane + 1], cs1);
    atomicAdd(&bss[2 * lane], ss0);
    atomicAdd(&bss[2 * lane + 1], ss1);
    __syncthreads();
    if (tid < CH) {
        atomicAdd(&g_colsum[tid], bsum[tid]);
        atomicAdd(&g_sumsq[tid],  bss[tid]);
    }
}

// ---------------------------------------------------------------------------
// K5: final GraphNorm, in-place, float4. var = E[h^2] - 2*am*mu + am^2.
// ---------------------------------------------------------------------------
__global__ void k_final(const float* __restrict__ gnw, const float* __restrict__ gnb,
                        const float* __restrict__ gna, float* __restrict__ out,
                        int N) {
    const float invN = 1.f / (float)N;
    const int t = blockIdx.x * blockDim.x + threadIdx.x;
    const int c0 = (t & 15) * 4;
    float am[4], w[4], b[4];
    #pragma unroll
    for (int j = 0; j < 4; j++) {
        int c = c0 + j;
        float mu  = g_colsum[c] * invN;
        float a   = gna[c] * mu;
        float ex2 = g_sumsq[c] * invN;
        float var = ex2 - 2.f * a * mu + a * a;
        am[j] = a;
        w[j]  = gnw[c] * rsqrtf(var + 1e-5f);
        b[j]  = gnb[c];
    }
    float4* o4 = reinterpret_cast<float4*>(out);
    const int total = N * 16;
    for (int i = t; i < total; i += gridDim.x * blockDim.x) {
        float4 h = o4[i];
        h.x = fmaf(h.x - am[0], w[0], b[0]);
        h.y = fmaf(h.y - am[1], w[1], b[1]);
        h.z = fmaf(h.z - am[2], w[2], b[2]);
        h.w = fmaf(h.w - am[3], w[3], b[3]);
        o4[i] = h;
    }
}

// ---------------------------------------------------------------------------
extern "C" void kernel_launch(void* const* d_in, const int* in_sizes, int n_in,
                              void* d_out, int out_size) {
    const float* x    = (const float*)d_in[0];
    const void*  ei   = d_in[1];
    const float* W0   = (const float*)d_in[2];
    const float* ln0w = (const float*)d_in[3];
    const float* ln0b = (const float*)d_in[4];
    const float* W1   = (const float*)d_in[5];
    const float* ln1w = (const float*)d_in[6];
    const float* ln1b = (const float*)d_in[7];
    const float* gnw  = (const float*)d_in[8];
    const float* gnb  = (const float*)d_in[9];
    const float* gna  = (const float*)d_in[10];

    const int N = in_sizes[0] / CH;
    const int E = in_sizes[1] / 2;
    float* out = (float*)d_out;

    // Host-side attribute set (not a stream op; safe during graph capture).
    cudaFuncSetAttribute(k_mlp, cudaFuncAttributeMaxDynamicSharedMemorySize,
                         SM_TOTAL);

    const int prep_blocks = (N * 32 + 255) / 256;
    k_prep<<<prep_blocks, 256>>>((const float2*)x, (const int*)ei, N, E); // 1
    k_bucket<<<(E + 255) / 256, 256>>>(ei, E);                            // 2
    k_gather<<<(N + 7) / 8, 256>>>(x, out, N);                            // 3

    const int rows_per_block = 8 * 16;                                    // 8 warps x 16
    const int mlp_blocks = (N + rows_per_block - 1) / rows_per_block;
    k_mlp<<<mlp_blocks, 256, SM_TOTAL>>>(W0, ln0w, ln0b,                  // 4 (profiled)
                                         W1, ln1w, ln1b, out, N);

    k_final<<<2048, 256>>>(gnw, gnb, gna, out, N);                        // 5
}